// round 12
// baseline (speedup 1.0000x reference)
#include <cuda_runtime.h>
#include <cuda_fp16.h>
#include <cstdint>

// DilatedMSA: fused QKV + 2-head attention, one CTA per (bl, head).
// Grid 1024, 512 threads (16 warps, 4/SMSP for latency hiding).
// Attention is KEY-SPLIT: warps 0-7 attend keys 0-127, warps 8-15 keys 128-255,
// over the same m32 row blocks. No-max softmax partials combine exactly:
// O = (O0+O1)/(l0+l1) via an smem partial buffer.
// All fragment loads via ldmatrix.x4; per-warp attention state fits 128 regs.

#define G    256
#define CDIM 128
#define HD   64

// smem layout (bytes); all fragment strides are 16 mod 128 -> LDSM conflict-free
#define XS_OFF 0        // x  [256][136]h = 69632  (later: partial-O [256][68] f32)
#define WS_OFF 69632    // W  [3][64][136]h = 52224 (later: l0 row sums [256] f32)
#define QS_OFF 121856   // Q  [256][72]h = 36864
#define KS_OFF 158720   // K  [256][72]h = 36864
#define VT_OFF 195584   // V^T[64][264]h = 33792 (vt[ch][key^swz(ch)])
#define SMEM_BYTES 229376

__device__ __forceinline__ void mma16816(float* c, const unsigned* a, unsigned b0, unsigned b1) {
    asm volatile(
        "mma.sync.aligned.m16n8k16.row.col.f32.f16.f16.f32 "
        "{%0,%1,%2,%3}, {%4,%5,%6,%7}, {%8,%9}, {%0,%1,%2,%3};\n"
        : "+f"(c[0]), "+f"(c[1]), "+f"(c[2]), "+f"(c[3])
        : "r"(a[0]), "r"(a[1]), "r"(a[2]), "r"(a[3]), "r"(b0), "r"(b1));
}

__device__ __forceinline__ void ldsm4(unsigned& r0, unsigned& r1, unsigned& r2, unsigned& r3,
                                      uint32_t saddr) {
    asm volatile("ldmatrix.sync.aligned.m8n8.x4.shared.b16 {%0,%1,%2,%3}, [%4];"
                 : "=r"(r0), "=r"(r1), "=r"(r2), "=r"(r3) : "r"(saddr));
}

__device__ __forceinline__ uint32_t s2u(const void* p) {
    uint32_t a;
    asm("{ .reg .u64 t; cvta.to.shared.u64 t, %1; cvt.u32.u64 %0, t; }" : "=r"(a) : "l"(p));
    return a;
}

__device__ __forceinline__ unsigned pack_h2(float lo, float hi) {
    __half2 h = __floats2half2_rn(lo, hi);
    return *(unsigned*)&h;
}

__global__ __launch_bounds__(512, 1)
void dmsa_kernel(const float* __restrict__ x,
                 const float* __restrict__ W,
                 const float* __restrict__ bias,
                 float* __restrict__ out)
{
    extern __shared__ char smem[];
    __half* xs = (__half*)(smem + XS_OFF);   // [256][136]
    __half* ws = (__half*)(smem + WS_OFF);   // [3][64][136]
    __half* qs = (__half*)(smem + QS_OFF);   // [256][72]
    __half* ks = (__half*)(smem + KS_OFF);   // [256][72]
    __half* vt = (__half*)(smem + VT_OFF);   // [64][264]
    const uint32_t sb = s2u(smem);

    const int tid  = threadIdx.x;
    const int lane = tid & 31;
    const int warp = tid >> 5;               // 0..15
    const int g4   = lane >> 2;
    const int t4   = lane & 3;
    const int bl   = blockIdx.x >> 1;
    const int h    = blockIdx.x & 1;

    // LDSM per-lane address components (same mapping as validated R8 kernel)
    const int qq = lane >> 3, rr = lane & 7;
    const int aRow  = ((qq & 1) << 3) + rr;
    const int aColB = (qq >> 1) << 4;
    const int bRow  = ((qq >> 1) << 3) + rr;
    const int bColB = (qq & 1) << 4;

    // ---------------- Phase 1a: stage x and all 3 W chunks ----------------
    {
        const float4* xg = (const float4*)(x + (size_t)bl * (G * CDIM));
        #pragma unroll
        for (int i = 0; i < 16; i++) {
            int f = tid + i * 512;           // 8192 float4
            int r = f >> 5, c4 = f & 31;
            float4 v = xg[f];
            *(__half2*)(xs + r * 136 + c4 * 4)     = __floats2half2_rn(v.x, v.y);
            *(__half2*)(xs + r * 136 + c4 * 4 + 2) = __floats2half2_rn(v.z, v.w);
        }
        #pragma unroll
        for (int i = 0; i < 12; i++) {
            int f = tid + i * 512;           // 6144 float4 (3 chunks x 64 rows x 32)
            int ch = f >> 11;
            int rem = f & 2047;
            int r = rem >> 5, c4 = rem & 31;
            const float4* wg = (const float4*)(W + ((size_t)ch * CDIM + h * HD + r) * CDIM);
            float4 v = wg[c4];
            __half* wrow = ws + ch * 8704 + r * 136;
            *(__half2*)(wrow + c4 * 4)     = __floats2half2_rn(v.x, v.y);
            *(__half2*)(wrow + c4 * 4 + 2) = __floats2half2_rn(v.z, v.w);
        }
    }
    __syncthreads();

    // ---------------- Phase 1b: QKV GEMM (16 warps, m16 x n64 each) ----------------
    const uint32_t sxs = sb + XS_OFF;
    const uint32_t sws = sb + WS_OFF;

    #pragma unroll
    for (int ch = 0; ch < 3; ch++) {
        float acc[8][4];
        #pragma unroll
        for (int nt = 0; nt < 8; nt++)
            #pragma unroll
            for (int q = 0; q < 4; q++) acc[nt][q] = 0.f;

        #pragma unroll
        for (int kk = 0; kk < 8; kk++) {
            unsigned a[4];
            ldsm4(a[0], a[1], a[2], a[3],
                  sxs + (uint32_t)((warp * 16 + aRow) * 272 + kk * 32 + aColB));
            #pragma unroll
            for (int p = 0; p < 4; p++) {
                unsigned b0, b1, b2, b3;
                ldsm4(b0, b1, b2, b3,
                      sws + (uint32_t)(ch * 17408 + (p * 16 + bRow) * 272 + kk * 32 + bColB));
                mma16816(acc[2*p],   a, b0, b1);
                mma16816(acc[2*p+1], a, b2, b3);
            }
        }

        // epilogue: +bias, fp16, store to qs/ks/vt (rows warp*16+g4, +8)
        #pragma unroll
        for (int nt = 0; nt < 8; nt++) {
            int dl = nt * 8 + 2 * t4;
            float2 bv = *(const float2*)(bias + ch * CDIM + h * HD + dl);
            float v0 = acc[nt][0] + bv.x;
            float v1 = acc[nt][1] + bv.y;
            float v2 = acc[nt][2] + bv.x;
            float v3 = acc[nt][3] + bv.y;
            int r = warp * 16 + g4;
            if (ch == 0) {
                *(__half2*)(qs + r * 72 + dl)       = __floats2half2_rn(v0, v1);
                *(__half2*)(qs + (r + 8) * 72 + dl) = __floats2half2_rn(v2, v3);
            } else if (ch == 1) {
                *(__half2*)(ks + r * 72 + dl)       = __floats2half2_rn(v0, v1);
                *(__half2*)(ks + (r + 8) * 72 + dl) = __floats2half2_rn(v2, v3);
            } else {
                int sw = ((dl >> 3) & 3) << 3;       // swizzle key index by channel/8
                vt[dl * 264 + (r ^ sw)]             = __float2half_rn(v0);
                vt[(dl + 1) * 264 + (r ^ sw)]       = __float2half_rn(v1);
                vt[dl * 264 + ((r + 8) ^ sw)]       = __float2half_rn(v2);
                vt[(dl + 1) * 264 + ((r + 8) ^ sw)] = __float2half_rn(v3);
            }
        }
    }
    __syncthreads();

    // ---------------- Phase 2: attention, key-split ----------------
    // warp w: rows mbase..mbase+31 (two m16 tiles), keys half*128..half*128+127
    const float csc = 0.088388347648318447f * 1.4426950408889634f;  // log2e/sqrt(128)
    const uint32_t sqs = sb + QS_OFF;
    const uint32_t sks = sb + KS_OFF;
    const uint32_t svt = sb + VT_OFF;
    const int mbase = (warp & 7) * 32;
    const int half  = warp >> 3;

    float o[2][8][4];
    #pragma unroll
    for (int mt = 0; mt < 2; mt++)
        #pragma unroll
        for (int nt = 0; nt < 8; nt++)
            #pragma unroll
            for (int q = 0; q < 4; q++) o[mt][nt][q] = 0.f;
    float lrow[2][2] = {{0.f, 0.f}, {0.f, 0.f}};
    unsigned pk[2][16];

    #pragma unroll
    for (int jl = 0; jl < 2; jl++) {             // this half's two 64-key tiles
        const int jg = half * 2 + jl;            // global key tile 0..3

        // S + softmax for both m16 tiles (s buffer reused; P packed immediately)
        #pragma unroll
        for (int mt = 0; mt < 2; mt++) {
            float s[8][4];
            #pragma unroll
            for (int nt = 0; nt < 8; nt++)
                #pragma unroll
                for (int q = 0; q < 4; q++) s[nt][q] = 0.f;

            #pragma unroll
            for (int kk = 0; kk < 4; kk++) {
                unsigned a[4];
                ldsm4(a[0], a[1], a[2], a[3],
                      sqs + (uint32_t)((mbase + mt * 16 + aRow) * 144 + kk * 32 + aColB));
                #pragma unroll
                for (int p = 0; p < 4; p++) {
                    unsigned b0, b1, b2, b3;
                    ldsm4(b0, b1, b2, b3,
                          sks + (uint32_t)((jg * 64 + p * 16 + bRow) * 144 + kk * 32 + bColB));
                    mma16816(s[2*p],   a, b0, b1);
                    mma16816(s[2*p+1], a, b2, b3);
                }
            }
            #pragma unroll
            for (int nt = 0; nt < 8; nt++) {
                float p0 = exp2f(s[nt][0] * csc);
                float p1 = exp2f(s[nt][1] * csc);
                float p2 = exp2f(s[nt][2] * csc);
                float p3 = exp2f(s[nt][3] * csc);
                lrow[mt][0] += p0 + p1;
                lrow[mt][1] += p2 + p3;
                pk[mt][2*nt]   = pack_h2(p0, p1);
                pk[mt][2*nt+1] = pack_h2(p2, p3);
            }
        }

        // PV: stream V once, accumulate both m16 tiles
        #pragma unroll
        for (int kk = 0; kk < 4; kk++) {
            int kbase = jg * 64 + kk * 16;       // key index (halves)
            #pragma unroll
            for (int p = 0; p < 4; p++) {
                int n   = p * 16 + bRow;         // output channel row
                int swh = (((n >> 3) & 3) << 3); // matches vt store swizzle
                uint32_t addr = svt + (uint32_t)(n * 528 +
                                 (((kbase + ((qq & 1) << 3)) ^ swh) << 1));
                unsigned b0, b1, b2, b3;
                ldsm4(b0, b1, b2, b3, addr);
                mma16816(o[0][2*p],   &pk[0][4*kk], b0, b1);
                mma16816(o[0][2*p+1], &pk[0][4*kk], b2, b3);
                mma16816(o[1][2*p],   &pk[1][4*kk], b0, b1);
                mma16816(o[1][2*p+1], &pk[1][4*kk], b2, b3);
            }
        }
    }

    // reduce row-sum partials across the quad (once, after all tiles)
    #pragma unroll
    for (int mt = 0; mt < 2; mt++)
        #pragma unroll
        for (int hh = 0; hh < 2; hh++) {
            lrow[mt][hh] += __shfl_xor_sync(0xffffffffu, lrow[mt][hh], 1);
            lrow[mt][hh] += __shfl_xor_sync(0xffffffffu, lrow[mt][hh], 2);
        }

    // ---------------- Phase 3: combine key-halves, normalize, store ----------------
    float* POB = (float*)(smem + XS_OFF);        // [256][68] f32 partial-O (x dead)
    float* l0b = (float*)(smem + WS_OFF);        // [256] f32 (W dead)

    if (half == 0) {                              // write raw partials
        #pragma unroll
        for (int mt = 0; mt < 2; mt++) {
            #pragma unroll
            for (int hh = 0; hh < 2; hh++) {
                int r = mbase + mt * 16 + hh * 8 + g4;
                if (t4 == 0) l0b[r] = lrow[mt][hh];
                #pragma unroll
                for (int nt = 0; nt < 8; nt++) {
                    int c = nt * 8 + 2 * t4;
                    float2 v = { o[mt][nt][2*hh], o[mt][nt][2*hh+1] };
                    *(float2*)(POB + r * 68 + c) = v;
                }
            }
        }
    }
    __syncthreads();

    if (half == 1) {                              // add own partial, normalize, write back
        #pragma unroll
        for (int mt = 0; mt < 2; mt++) {
            #pragma unroll
            for (int hh = 0; hh < 2; hh++) {
                int r = mbase + mt * 16 + hh * 8 + g4;
                float inv = 1.0f / (l0b[r] + lrow[mt][hh]);
                #pragma unroll
                for (int nt = 0; nt < 8; nt++) {
                    int c = nt * 8 + 2 * t4;
                    float2 pv = *(const float2*)(POB + r * 68 + c);
                    float2 v = { (pv.x + o[mt][nt][2*hh]) * inv,
                                 (pv.y + o[mt][nt][2*hh+1]) * inv };
                    *(float2*)(POB + r * 68 + c) = v;
                }
            }
        }
    }
    __syncthreads();

    {
        float* og = out + (size_t)bl * (G * CDIM) + h * HD;
        #pragma unroll
        for (int i = 0; i < 8; i++) {
            int f = tid + i * 512;                // 4096 float4
            int r = f >> 4, c4 = (f & 15) * 4;
            float4 v = *(const float4*)(POB + r * 68 + c4);
            *(float4*)(og + (size_t)r * CDIM + c4) = v;
        }
    }
}

extern "C" void kernel_launch(void* const* d_in, const int* in_sizes, int n_in,
                              void* d_out, int out_size)
{
    // identify inputs by size: x=16777216, W=49152, b=384
    const float* x = 0; const float* W = 0; const float* b = 0;
    for (int i = 0; i < n_in; i++) {
        if (in_sizes[i] == 8 * 64 * 256 * 128) x = (const float*)d_in[i];
        else if (in_sizes[i] == 3 * 128 * 128) W = (const float*)d_in[i];
        else if (in_sizes[i] == 3 * 128)       b = (const float*)d_in[i];
    }
    float* out = (float*)d_out;

    cudaFuncSetAttribute(dmsa_kernel, cudaFuncAttributeMaxDynamicSharedMemorySize, SMEM_BYTES);
    dmsa_kernel<<<1024, 512, SMEM_BYTES>>>(x, W, b, out);
}

// round 15
// speedup vs baseline: 1.6419x; 1.6419x over previous
#include <cuda_runtime.h>
#include <cuda_fp16.h>
#include <cstdint>

// DilatedMSA: fused QKV + 2-head attention, one CTA per (bl, head).
// Grid 1024, 256 threads (8 warps), warp tile m32 x n64.
// Register-budget redesign of the R8 kernel:
//  - Q kept entirely in registers (QKV C-frags repacked as mma A-frags; no Q smem)
//  - S computed one m16 tile at a time, P packed fp16 immediately
//  => peak ~190 live regs (vs 255): ptxas gets headroom to pipeline LDSM ahead
//     of mma chains. 512-thread variants spill (R10: DRAM 26%) — do not revisit.
// No-max softmax (scores bounded; validated rel_err ~2.6e-4).

#define G    256
#define CDIM 128
#define HD   64

// smem layout (bytes); fragment strides 16 mod 128 -> LDSM conflict-free
#define XS_OFF 0        // x  [256][136]h = 69632  (later O stage [256][68] f32)
#define WS_OFF 69632    // W  [3][64][136]h = 52224
#define KS_OFF 121856   // K  [256][72]h = 36864
#define VT_OFF 158720   // V^T[64][264]h = 33792 (vt[ch][key^swz(ch)])
#define SMEM_BYTES 192512

__device__ __forceinline__ void mma16816(float* c, const unsigned* a, unsigned b0, unsigned b1) {
    asm volatile(
        "mma.sync.aligned.m16n8k16.row.col.f32.f16.f16.f32 "
        "{%0,%1,%2,%3}, {%4,%5,%6,%7}, {%8,%9}, {%0,%1,%2,%3};\n"
        : "+f"(c[0]), "+f"(c[1]), "+f"(c[2]), "+f"(c[3])
        : "r"(a[0]), "r"(a[1]), "r"(a[2]), "r"(a[3]), "r"(b0), "r"(b1));
}

__device__ __forceinline__ void ldsm4(unsigned& r0, unsigned& r1, unsigned& r2, unsigned& r3,
                                      uint32_t saddr) {
    asm volatile("ldmatrix.sync.aligned.m8n8.x4.shared.b16 {%0,%1,%2,%3}, [%4];"
                 : "=r"(r0), "=r"(r1), "=r"(r2), "=r"(r3) : "r"(saddr));
}

__device__ __forceinline__ uint32_t s2u(const void* p) {
    uint32_t a;
    asm("{ .reg .u64 t; cvta.to.shared.u64 t, %1; cvt.u32.u64 %0, t; }" : "=r"(a) : "l"(p));
    return a;
}

__device__ __forceinline__ unsigned pack_h2(float lo, float hi) {
    __half2 h = __floats2half2_rn(lo, hi);
    return *(unsigned*)&h;
}

__global__ __launch_bounds__(256, 1)
void dmsa_kernel(const float* __restrict__ x,
                 const float* __restrict__ W,
                 const float* __restrict__ bias,
                 float* __restrict__ out)
{
    extern __shared__ char smem[];
    __half* xs = (__half*)(smem + XS_OFF);   // [256][136]
    __half* ws = (__half*)(smem + WS_OFF);   // [3][64][136]
    __half* ks = (__half*)(smem + KS_OFF);   // [256][72]
    __half* vt = (__half*)(smem + VT_OFF);   // [64][264]
    const uint32_t sb = s2u(smem);

    const int tid  = threadIdx.x;
    const int lane = tid & 31;
    const int warp = tid >> 5;               // 0..7
    const int g4   = lane >> 2;
    const int t4   = lane & 3;
    const int bl   = blockIdx.x >> 1;
    const int h    = blockIdx.x & 1;

    // LDSM per-lane address components (validated in R8)
    const int qq = lane >> 3, rr = lane & 7;
    const int aRow  = ((qq & 1) << 3) + rr;
    const int aColB = (qq >> 1) << 4;
    const int bRow  = ((qq >> 1) << 3) + rr;
    const int bColB = (qq & 1) << 4;

    // ---------------- Phase 1a: stage x and all 3 W chunks ----------------
    {
        const float4* xg = (const float4*)(x + (size_t)bl * (G * CDIM));
        #pragma unroll
        for (int i = 0; i < 32; i++) {
            int f = tid + i * 256;           // 8192 float4
            int r = f >> 5, c4 = f & 31;
            float4 v = xg[f];
            *(__half2*)(xs + r * 136 + c4 * 4)     = __floats2half2_rn(v.x, v.y);
            *(__half2*)(xs + r * 136 + c4 * 4 + 2) = __floats2half2_rn(v.z, v.w);
        }
        #pragma unroll
        for (int i = 0; i < 24; i++) {
            int f = tid + i * 256;           // 6144 float4 (3 chunks x 64 rows x 32)
            int ch = f >> 11;
            int rem = f & 2047;
            int r = rem >> 5, c4 = rem & 31;
            const float4* wg = (const float4*)(W + ((size_t)ch * CDIM + h * HD + r) * CDIM);
            float4 v = wg[c4];
            __half* wrow = ws + ch * 8704 + r * 136;
            *(__half2*)(wrow + c4 * 4)     = __floats2half2_rn(v.x, v.y);
            *(__half2*)(wrow + c4 * 4 + 2) = __floats2half2_rn(v.z, v.w);
        }
    }
    __syncthreads();

    // ---------------- Phase 1b: QKV GEMM (per warp m32 x n64) ----------------
    const uint32_t sxs = sb + XS_OFF;
    const uint32_t sws = sb + WS_OFF;
    const int r0 = warp * 32;

    unsigned qA[4][2][4];                    // Q A-fragments, built in ch==0 epilogue

    #pragma unroll
    for (int ch = 0; ch < 3; ch++) {
        float acc[2][8][4];
        #pragma unroll
        for (int mi = 0; mi < 2; mi++)
            #pragma unroll
            for (int nt = 0; nt < 8; nt++)
                #pragma unroll
                for (int q = 0; q < 4; q++) acc[mi][nt][q] = 0.f;

        #pragma unroll
        for (int kk = 0; kk < 8; kk++) {
            unsigned a0[4], a1[4];
            ldsm4(a0[0], a0[1], a0[2], a0[3],
                  sxs + (uint32_t)((r0 + aRow) * 272 + kk * 32 + aColB));
            ldsm4(a1[0], a1[1], a1[2], a1[3],
                  sxs + (uint32_t)((r0 + 16 + aRow) * 272 + kk * 32 + aColB));
            #pragma unroll
            for (int p = 0; p < 4; p++) {
                unsigned b0, b1, b2, b3;
                ldsm4(b0, b1, b2, b3,
                      sws + (uint32_t)(ch * 17408 + (p * 16 + bRow) * 272 + kk * 32 + bColB));
                mma16816(acc[0][2*p],   a0, b0, b1);
                mma16816(acc[0][2*p+1], a0, b2, b3);
                mma16816(acc[1][2*p],   a1, b0, b1);
                mma16816(acc[1][2*p+1], a1, b2, b3);
            }
        }

        // epilogue: +bias; ch0 -> qA regs, ch1 -> ks, ch2 -> vt
        #pragma unroll
        for (int mi = 0; mi < 2; mi++) {
            #pragma unroll
            for (int nt = 0; nt < 8; nt++) {
                int dl = nt * 8 + 2 * t4;
                float2 bv = *(const float2*)(bias + ch * CDIM + h * HD + dl);
                float v0 = acc[mi][nt][0] + bv.x;
                float v1 = acc[mi][nt][1] + bv.y;
                float v2 = acc[mi][nt][2] + bv.x;
                float v3 = acc[mi][nt][3] + bv.y;
                int r = r0 + mi * 16 + g4;
                if (ch == 0) {
                    // C-frag -> A-frag repack (k-block kk = nt>>1)
                    int kkq = nt >> 1;
                    if ((nt & 1) == 0) {
                        qA[kkq][mi][0] = pack_h2(v0, v1);
                        qA[kkq][mi][1] = pack_h2(v2, v3);
                    } else {
                        qA[kkq][mi][2] = pack_h2(v0, v1);
                        qA[kkq][mi][3] = pack_h2(v2, v3);
                    }
                } else if (ch == 1) {
                    *(__half2*)(ks + r * 72 + dl)       = __floats2half2_rn(v0, v1);
                    *(__half2*)(ks + (r + 8) * 72 + dl) = __floats2half2_rn(v2, v3);
                } else {
                    int sw = ((dl >> 3) & 3) << 3;       // swizzle key index by channel/8
                    vt[dl * 264 + (r ^ sw)]             = __float2half_rn(v0);
                    vt[(dl + 1) * 264 + (r ^ sw)]       = __float2half_rn(v1);
                    vt[dl * 264 + ((r + 8) ^ sw)]       = __float2half_rn(v2);
                    vt[(dl + 1) * 264 + ((r + 8) ^ sw)] = __float2half_rn(v3);
                }
            }
        }
    }
    __syncthreads();

    // ---------------- Phase 2: attention (per warp 32 rows) ----------------
    const float csc = 0.088388347648318447f * 1.4426950408889634f;  // log2e/sqrt(128)
    const uint32_t sks = sb + KS_OFF;
    const uint32_t svt = sb + VT_OFF;

    float o[2][8][4];
    #pragma unroll
    for (int mt = 0; mt < 2; mt++)
        #pragma unroll
        for (int nt = 0; nt < 8; nt++)
            #pragma unroll
            for (int q = 0; q < 4; q++) o[mt][nt][q] = 0.f;
    float lrow[2][2] = {{0.f, 0.f}, {0.f, 0.f}};

    #pragma unroll
    for (int j = 0; j < 4; j++) {            // key tiles of 64
        unsigned pk[2][16];

        // S + softmax per m16 tile (S transient: 32 regs; P packed immediately)
        #pragma unroll
        for (int mt = 0; mt < 2; mt++) {
            float s[8][4];
            #pragma unroll
            for (int nt = 0; nt < 8; nt++)
                #pragma unroll
                for (int q = 0; q < 4; q++) s[nt][q] = 0.f;

            #pragma unroll
            for (int kk = 0; kk < 4; kk++) {
                #pragma unroll
                for (int p = 0; p < 4; p++) {
                    unsigned b0, b1, b2, b3;
                    ldsm4(b0, b1, b2, b3,
                          sks + (uint32_t)((j * 64 + p * 16 + bRow) * 144 + kk * 32 + bColB));
                    mma16816(s[2*p],   qA[kk][mt], b0, b1);
                    mma16816(s[2*p+1], qA[kk][mt], b2, b3);
                }
            }
            #pragma unroll
            for (int nt = 0; nt < 8; nt++) {
                float p0 = exp2f(s[nt][0] * csc);
                float p1 = exp2f(s[nt][1] * csc);
                float p2 = exp2f(s[nt][2] * csc);
                float p3 = exp2f(s[nt][3] * csc);
                lrow[mt][0] += p0 + p1;
                lrow[mt][1] += p2 + p3;
                pk[mt][2*nt]   = pack_h2(p0, p1);
                pk[mt][2*nt+1] = pack_h2(p2, p3);
            }
        }

        // PV: stream V once, accumulate both m16 tiles
        #pragma unroll
        for (int kk = 0; kk < 4; kk++) {
            int kbase = j * 64 + kk * 16;    // key index (halves)
            #pragma unroll
            for (int p = 0; p < 4; p++) {
                int n   = p * 16 + bRow;     // output channel row
                int swh = (((n >> 3) & 3) << 3);
                uint32_t addr = svt + (uint32_t)(n * 528 +
                                 (((kbase + ((qq & 1) << 3)) ^ swh) << 1));
                unsigned b0, b1, b2, b3;
                ldsm4(b0, b1, b2, b3, addr);
                mma16816(o[0][2*p],   &pk[0][4*kk], b0, b1);
                mma16816(o[0][2*p+1], &pk[0][4*kk], b2, b3);
                mma16816(o[1][2*p],   &pk[1][4*kk], b0, b1);
                mma16816(o[1][2*p+1], &pk[1][4*kk], b2, b3);
            }
        }
    }

    // quad-reduce row sums
    #pragma unroll
    for (int mt = 0; mt < 2; mt++)
        #pragma unroll
        for (int hh = 0; hh < 2; hh++) {
            lrow[mt][hh] += __shfl_xor_sync(0xffffffffu, lrow[mt][hh], 1);
            lrow[mt][hh] += __shfl_xor_sync(0xffffffffu, lrow[mt][hh], 2);
        }

    // ---------------- Phase 3: normalize + coalesced store via smem ----------------
    float* osm = (float*)(smem + XS_OFF);    // [256][68] f32, reuses x region
    __syncthreads();                          // xs fragment reads done CTA-wide
    #pragma unroll
    for (int mt = 0; mt < 2; mt++) {
        #pragma unroll
        for (int hh = 0; hh < 2; hh++) {
            float inv = 1.0f / lrow[mt][hh];
            int r = r0 + mt * 16 + hh * 8 + g4;
            #pragma unroll
            for (int nt = 0; nt < 8; nt++) {
                int c = nt * 8 + 2 * t4;
                float2 v = { o[mt][nt][2*hh] * inv, o[mt][nt][2*hh+1] * inv };
                *(float2*)(osm + r * 68 + c) = v;
            }
        }
    }
    __syncthreads();

    {
        float* og = out + (size_t)bl * (G * CDIM) + h * HD;
        #pragma unroll
        for (int i = 0; i < 16; i++) {
            int f = tid + i * 256;            // 4096 float4
            int r = f >> 4, c4 = (f & 15) * 4;
            float4 v = *(const float4*)(osm + r * 68 + c4);
            *(float4*)(og + (size_t)r * CDIM + c4) = v;
        }
    }
}

extern "C" void kernel_launch(void* const* d_in, const int* in_sizes, int n_in,
                              void* d_out, int out_size)
{
    // identify inputs by size: x=16777216, W=49152, b=384
    const float* x = 0; const float* W = 0; const float* b = 0;
    for (int i = 0; i < n_in; i++) {
        if (in_sizes[i] == 8 * 64 * 256 * 128) x = (const float*)d_in[i];
        else if (in_sizes[i] == 3 * 128 * 128) W = (const float*)d_in[i];
        else if (in_sizes[i] == 3 * 128)       b = (const float*)d_in[i];
    }
    float* out = (float*)d_out;

    cudaFuncSetAttribute(dmsa_kernel, cudaFuncAttributeMaxDynamicSharedMemorySize, SMEM_BYTES);
    dmsa_kernel<<<1024, 256, SMEM_BYTES>>>(x, W, b, out);
}